// round 2
// baseline (speedup 1.0000x reference)
#include <cuda_runtime.h>

// X, Y: [64, 1, 512, 512] float32
// 3x3 separable window (w = outer(a, a), a = [WA, WB, WA]), SAME conv,
// crop [5:-5,5:-5] -> [64,502,502]; loss = sum_b mean_hw(sxx*syy - 2*sxy)

#define FULLMASK 0xFFFFFFFFu
#define WA 0.30780134f
#define WB 0.38439735f

typedef unsigned long long u64;

__device__ float g_part[4096];

// ---- packed f32x2 helpers (Blackwell) ----
struct F2 { u64 v; };
__device__ __forceinline__ F2 pk(float a, float b) {
    F2 r; asm("mov.b64 %0, {%1, %2};" : "=l"(r.v) : "f"(a), "f"(b)); return r;
}
__device__ __forceinline__ void unpk(F2 a, float& x, float& y) {
    asm("mov.b64 {%0, %1}, %2;" : "=f"(x), "=f"(y) : "l"(a.v));
}
__device__ __forceinline__ F2 f2add(F2 a, F2 b) {
    F2 r; asm("add.rn.f32x2 %0, %1, %2;" : "=l"(r.v) : "l"(a.v), "l"(b.v)); return r;
}
__device__ __forceinline__ F2 f2mul(F2 a, F2 b) {
    F2 r; asm("mul.rn.f32x2 %0, %1, %2;" : "=l"(r.v) : "l"(a.v), "l"(b.v)); return r;
}
__device__ __forceinline__ F2 f2fma(F2 a, F2 b, F2 c) {
    F2 r; asm("fma.rn.f32x2 %0, %1, %2, %3;" : "=l"(r.v) : "l"(a.v), "l"(b.v), "l"(c.v)); return r;
}

// horizontal 3-tap pass for one input row: 5 fields x 2 f32x2 pairs
__device__ __forceinline__ void hrow(const float* __restrict__ Xr,
                                     const float* __restrict__ Yr,
                                     int ib, int hb, int lane,
                                     F2 WAv, F2 WBv, F2 hh[5][2]) {
    float4 xv = *(const float4*)(Xr + ib);
    float4 yv = *(const float4*)(Yr + ib);
    float x4 = __shfl_down_sync(FULLMASK, xv.x, 1);
    float x5 = __shfl_down_sync(FULLMASK, xv.y, 1);
    float y4 = __shfl_down_sync(FULLMASK, yv.x, 1);
    float y5 = __shfl_down_sync(FULLMASK, yv.y, 1);
    if (lane == 31) {   // right halo for last lane via extra float2 load
        float2 ex = *(const float2*)(Xr + hb);
        float2 ey = *(const float2*)(Yr + hb);
        x4 = ex.x; x5 = ex.y; y4 = ey.x; y5 = ey.y;
    }
    F2 XA[5] = { pk(xv.x, xv.y), pk(xv.y, xv.z), pk(xv.z, xv.w), pk(xv.w, x4), pk(x4, x5) };
    F2 YA[5] = { pk(yv.x, yv.y), pk(yv.y, yv.z), pk(yv.z, yv.w), pk(yv.w, y4), pk(y4, y5) };
#pragma unroll
    for (int p = 0; p < 2; p++) {
        F2 a0 = XA[2*p], a1 = XA[2*p+1], a2 = XA[2*p+2];
        F2 b0 = YA[2*p], b1 = YA[2*p+1], b2 = YA[2*p+2];
        hh[0][p] = f2fma(WAv, f2add(a0, a2), f2mul(WBv, a1));
        hh[1][p] = f2fma(WAv, f2add(b0, b2), f2mul(WBv, b1));
        hh[2][p] = f2fma(WAv, f2add(f2mul(a0, a0), f2mul(a2, a2)), f2mul(WBv, f2mul(a1, a1)));
        hh[3][p] = f2fma(WAv, f2add(f2mul(b0, b0), f2mul(b2, b2)), f2mul(WBv, f2mul(b1, b1)));
        hh[4][p] = f2fma(WAv, f2add(f2mul(a0, b0), f2mul(a2, b2)), f2mul(WBv, f2mul(a1, b1)));
    }
}

__global__ void __launch_bounds__(128)
loss_kernel(const float* __restrict__ X, const float* __restrict__ Y) {
    const int lane = threadIdx.x & 31;
    const int unit = blockIdx.x * 4 + (threadIdx.x >> 5);  // 4096 warp units
    const int b = unit >> 6;
    const int s = (unit >> 4) & 3;   // column stripe (128 output cols)
    const int t = unit & 15;         // row strip (32 output rows)

    const int cb   = 5 + 128 * s;
    const int r0   = 5 + 32 * t;
    const int rend = min(r0 + 32, 507);

    const int j0 = cb + 4 * lane;
    const int ib = min(j0 - 1, 508);
    const int hb = min(j0 + 3, 510);

    const float* Xb = X + ((size_t)b << 18);
    const float* Yb = Y + ((size_t)b << 18);

    const F2 WAv = pk(WA, WA);
    const F2 WBv = pk(WB, WB);
    const F2 M1  = pk(-1.0f, -1.0f);
    const F2 M2  = pk(-2.0f, -2.0f);
    const F2 mask[2] = {
        pk(j0     < 507 ? 1.0f : 0.0f, j0 + 1 < 507 ? 1.0f : 0.0f),
        pk(j0 + 2 < 507 ? 1.0f : 0.0f, j0 + 3 < 507 ? 1.0f : 0.0f)
    };

    F2 hh[5][2], Vp[5][2], Vq[5][2];

    // prime with input rows r0-1, r0
    hrow(Xb + (size_t)(r0 - 1) * 512, Yb + (size_t)(r0 - 1) * 512, ib, hb, lane, WAv, WBv, hh);
#pragma unroll
    for (int f = 0; f < 5; f++)
#pragma unroll
        for (int p = 0; p < 2; p++) Vq[f][p] = f2mul(WAv, hh[f][p]);

    hrow(Xb + (size_t)r0 * 512, Yb + (size_t)r0 * 512, ib, hb, lane, WAv, WBv, hh);
#pragma unroll
    for (int f = 0; f < 5; f++)
#pragma unroll
        for (int p = 0; p < 2; p++) {
            Vp[f][p] = f2fma(WBv, hh[f][p], Vq[f][p]);
            Vq[f][p] = f2mul(WAv, hh[f][p]);
        }

    F2 acc[2] = { pk(0.0f, 0.0f), pk(0.0f, 0.0f) };

#pragma unroll 2
    for (int i = r0 + 1; i <= rend; ++i) {
        hrow(Xb + (size_t)i * 512, Yb + (size_t)i * 512, ib, hb, lane, WAv, WBv, hh);
#pragma unroll
        for (int p = 0; p < 2; p++) {
            // finish output row i-1
            F2 vx  = f2fma(WAv, hh[0][p], Vp[0][p]);
            F2 vy  = f2fma(WAv, hh[1][p], Vp[1][p]);
            F2 vxx = f2fma(WAv, hh[2][p], Vp[2][p]);
            F2 vyy = f2fma(WAv, hh[3][p], Vp[3][p]);
            F2 vxy = f2fma(WAv, hh[4][p], Vp[4][p]);
            F2 nvx = f2mul(vx, M1);
            F2 nvy = f2mul(vy, M1);
            F2 sxx = f2fma(nvx, vx, vxx);
            F2 syy = f2fma(nvy, vy, vyy);
            F2 sxy = f2fma(nvx, vy, vxy);
            acc[p] = f2fma(mask[p], f2fma(sxx, syy, f2mul(M2, sxy)), acc[p]);
            // roll vertical accumulators
#pragma unroll
            for (int f = 0; f < 5; f++) {
                Vp[f][p] = f2fma(WBv, hh[f][p], Vq[f][p]);
                Vq[f][p] = f2mul(WAv, hh[f][p]);
            }
        }
    }

    float a0, a1, a2, a3;
    unpk(acc[0], a0, a1);
    unpk(acc[1], a2, a3);
    float acs = (a0 + a1) + (a2 + a3);
#pragma unroll
    for (int o = 16; o > 0; o >>= 1) acs += __shfl_xor_sync(FULLMASK, acs, o);
    if (lane == 0) g_part[unit] = acs;   // plain store: no init kernel needed
}

__global__ void __launch_bounds__(256) finalize_kernel(float* __restrict__ out) {
    __shared__ double sh[256];
    int tid = threadIdx.x;
    double s = 0.0;
#pragma unroll
    for (int i = tid; i < 4096; i += 256) s += (double)g_part[i];
    sh[tid] = s;
    __syncthreads();
    for (int o = 128; o > 0; o >>= 1) {
        if (tid < o) sh[tid] += sh[tid + o];
        __syncthreads();
    }
    if (tid == 0) out[0] = (float)(sh[0] * (1.0 / 252004.0));
}

extern "C" void kernel_launch(void* const* d_in, const int* in_sizes, int n_in,
                              void* d_out, int out_size) {
    const float* X = (const float*)d_in[0];
    const float* Y = (const float*)d_in[1];
    float* out = (float*)d_out;

    loss_kernel<<<1024, 128>>>(X, Y);   // 4096 warps: 64 imgs x 4 stripes x 16 strips
    finalize_kernel<<<1, 256>>>(out);
}

// round 3
// speedup vs baseline: 1.4000x; 1.4000x over previous
#include <cuda_runtime.h>

// X, Y: [64, 1, 512, 512] float32
// 3x3 separable window (w = outer(a, a), a = [WA, WB, WA]), SAME conv,
// crop [5:-5,5:-5] -> [64,502,502]; loss = sum_b mean_hw(sxx*syy - 2*sxy)

#define FULLMASK 0xFFFFFFFFu
#define WA 0.30780134f
#define WB 0.38439735f

__device__ float g_part[1024];
__device__ unsigned int g_cnt = 0;

struct H5 { float x[2], y[2], xx[2], yy[2], xy[2]; };

// horizontal 3-tap pass for one input row; lane owns 2 output cols.
// Needs input cols j0-1..j0+2 -> two aligned float2 loads per array, no shuffles.
__device__ __forceinline__ void hrow(const float* __restrict__ Xr,
                                     const float* __restrict__ Yr,
                                     int ib, int hb, H5& h) {
    float2 xa = *(const float2*)(Xr + ib);
    float2 xb = *(const float2*)(Xr + hb);
    float2 ya = *(const float2*)(Yr + ib);
    float2 yb = *(const float2*)(Yr + hb);
    float xs[4] = {xa.x, xa.y, xb.x, xb.y};
    float ys[4] = {ya.x, ya.y, yb.x, yb.y};
    float q[4], r[4], p[4];
#pragma unroll
    for (int k = 0; k < 4; k++) {
        q[k] = xs[k] * xs[k];
        r[k] = ys[k] * ys[k];
        p[k] = xs[k] * ys[k];
    }
#pragma unroll
    for (int k = 0; k < 2; k++) {
        // fmaf(const, reg, fmaf(const, reg, const*reg)) -> all FFMA/FMUL imm forms
        h.x[k]  = fmaf(WA, xs[k], fmaf(WB, xs[k + 1], WA * xs[k + 2]));
        h.y[k]  = fmaf(WA, ys[k], fmaf(WB, ys[k + 1], WA * ys[k + 2]));
        h.xx[k] = fmaf(WA, q[k],  fmaf(WB, q[k + 1],  WA * q[k + 2]));
        h.yy[k] = fmaf(WA, r[k],  fmaf(WB, r[k + 1],  WA * r[k + 2]));
        h.xy[k] = fmaf(WA, p[k],  fmaf(WB, p[k + 1],  WA * p[k + 2]));
    }
}

__global__ void __launch_bounds__(128, 7)
loss_kernel(const float* __restrict__ X, const float* __restrict__ Y,
            float* __restrict__ out) {
    const int lane = threadIdx.x & 31;
    const int wid  = threadIdx.x >> 5;
    const int unit = blockIdx.x * 4 + wid;    // 4096 warp units
    const int b = unit >> 6;                  // image
    const int s = (unit >> 3) & 7;            // column stripe (64 output cols)
    const int t = unit & 7;                   // row strip (64 output rows)

    const int cb   = 5 + 64 * s;
    const int r0   = 5 + 64 * t;
    const int rend = min(r0 + 64, 507);       // outputs rows r0 .. rend-1

    const int j0 = cb + 2 * lane;             // first of 2 output cols
    const int ib = min(j0 - 1, 508);          // float2 base (even -> 8B aligned)
    const int hb = min(j0 + 1, 510);          // float2 base (even -> 8B aligned)

    const float* Xb = X + ((size_t)b << 18);
    const float* Yb = Y + ((size_t)b << 18);

    const float mk[2] = { (j0 < 507) ? 1.0f : 0.0f,
                          (j0 + 1 < 507) ? 1.0f : 0.0f };

    H5 h;
    float Vp[5][2], Vq[5][2];

    // prime: input row r0-1 seeds Vq (coeff WA toward output row r0)
    hrow(Xb + (size_t)(r0 - 1) * 512, Yb + (size_t)(r0 - 1) * 512, ib, hb, h);
    {
        const float* hf = &h.x[0];
#pragma unroll
        for (int f = 0; f < 5; f++)
#pragma unroll
            for (int k = 0; k < 2; k++) Vq[f][k] = WA * hf[f * 2 + k];
    }
    // prime: input row r0 -> Vp for output r0; Vq seeds output r0+1
    hrow(Xb + (size_t)r0 * 512, Yb + (size_t)r0 * 512, ib, hb, h);
    {
        const float* hf = &h.x[0];
#pragma unroll
        for (int f = 0; f < 5; f++)
#pragma unroll
            for (int k = 0; k < 2; k++) {
                Vp[f][k] = fmaf(WB, hf[f * 2 + k], Vq[f][k]);
                Vq[f][k] = WA * hf[f * 2 + k];
            }
    }

    float acc0 = 0.0f, acc1 = 0.0f;

#pragma unroll 2
    for (int i = r0 + 1; i <= rend; ++i) {
        hrow(Xb + (size_t)i * 512, Yb + (size_t)i * 512, ib, hb, h);
        const float* hf = &h.x[0];
#pragma unroll
        for (int k = 0; k < 2; k++) {
            // finish output row i-1 (all imm-form FFMA)
            float vx  = fmaf(WA, hf[0 * 2 + k], Vp[0][k]);
            float vy  = fmaf(WA, hf[1 * 2 + k], Vp[1][k]);
            float vxx = fmaf(WA, hf[2 * 2 + k], Vp[2][k]);
            float vyy = fmaf(WA, hf[3 * 2 + k], Vp[3][k]);
            float vxy = fmaf(WA, hf[4 * 2 + k], Vp[4][k]);
            float sxx = fmaf(-vx, vx, vxx);
            float syy = fmaf(-vy, vy, vyy);
            float sxy = fmaf(-vx, vy, vxy);
            float l   = fmaf(sxx, syy, -2.0f * sxy);
            if (k == 0) acc0 = fmaf(mk[0], l, acc0);
            else        acc1 = fmaf(mk[1], l, acc1);
            // roll vertical accumulators (all imm-form)
#pragma unroll
            for (int f = 0; f < 5; f++) {
                Vp[f][k] = fmaf(WB, hf[f * 2 + k], Vq[f][k]);
                Vq[f][k] = WA * hf[f * 2 + k];
            }
        }
    }

    // warp -> block -> grid reduction (last block finalizes; no extra launches)
    float acs = acc0 + acc1;
#pragma unroll
    for (int o = 16; o > 0; o >>= 1) acs += __shfl_xor_sync(FULLMASK, acs, o);

    __shared__ float sp[4];
    __shared__ bool is_last;
    __shared__ double sh[128];
    if (lane == 0) sp[wid] = acs;
    __syncthreads();
    if (threadIdx.x == 0) {
        g_part[blockIdx.x] = (sp[0] + sp[1]) + (sp[2] + sp[3]);
        __threadfence();
        unsigned r = atomicAdd(&g_cnt, 1u);
        is_last = (r == gridDim.x - 1);
    }
    __syncthreads();
    if (is_last) {
        __threadfence();
        double ds = 0.0;
#pragma unroll
        for (int i = threadIdx.x; i < 1024; i += 128) ds += (double)g_part[i];
        sh[threadIdx.x] = ds;
        __syncthreads();
        for (int o = 64; o > 0; o >>= 1) {
            if (threadIdx.x < o) sh[threadIdx.x] += sh[threadIdx.x + o];
            __syncthreads();
        }
        if (threadIdx.x == 0) {
            out[0] = (float)(sh[0] * (1.0 / 252004.0));
            g_cnt = 0;   // reset for next graph replay (deterministic)
        }
    }
}

extern "C" void kernel_launch(void* const* d_in, const int* in_sizes, int n_in,
                              void* d_out, int out_size) {
    const float* X = (const float*)d_in[0];
    const float* Y = (const float*)d_in[1];
    float* out = (float*)d_out;

    // 4096 warps = 64 images x 8 col-stripes(64) x 8 row-strips(64); 4 warps/block
    loss_kernel<<<1024, 128>>>(X, Y, out);
}

// round 4
// speedup vs baseline: 1.4737x; 1.0526x over previous
#include <cuda_runtime.h>

// X, Y: [64, 1, 512, 512] float32
// 3x3 separable window (w = outer(g,g), g = [WA, WB, WA]), SAME conv,
// crop [5:-5,5:-5] -> [64,502,502]; loss = sum_b mean_hw(sxx*syy - 2*sxy)
// Identity used: sum(loss) = sum(sxx*syy) + 2*sum(mu_x*mu_y) - 2*sum_crop C(xy)
// and sum_crop C(xy) == sum over input pixels of A(r)*A(c)*x*y  (exact for the
// separable filter; A=1 interior, WA/WA+WB on the 2-px rim of rows/cols 4..507).

#define FULLMASK 0xFFFFFFFFu
#define WA  0.30780134f
#define WB  0.38439735f
#define WAB 0.69219869f   // WA + WB

__device__ float g_part[1024];
__device__ unsigned int g_cnt = 0;

struct RowD { float x0, x1, x2, x3, y0, y1, y2, y3; };

__device__ __forceinline__ RowD ldrow(const float* __restrict__ Xr,
                                      const float* __restrict__ Yr,
                                      int ib, int hb) {
    RowD d;
    float2 xa = *(const float2*)(Xr + ib);
    float2 xb = *(const float2*)(Xr + hb);
    float2 ya = *(const float2*)(Yr + ib);
    float2 yb = *(const float2*)(Yr + hb);
    d.x0 = xa.x; d.x1 = xa.y; d.x2 = xb.x; d.x3 = xb.y;
    d.y0 = ya.x; d.y1 = ya.y; d.y2 = yb.x; d.y3 = yb.y;
    return d;
}

// horizontal 3-taps for the 4 conv fields at the lane's 2 output cols (imm-form)
__device__ __forceinline__ void htap(const RowD& d,
                                     float hx[2], float hy[2],
                                     float hxx[2], float hyy[2]) {
    float q0 = d.x0 * d.x0, q1 = d.x1 * d.x1, q2 = d.x2 * d.x2, q3 = d.x3 * d.x3;
    float r0 = d.y0 * d.y0, r1 = d.y1 * d.y1, r2 = d.y2 * d.y2, r3 = d.y3 * d.y3;
    hx[0]  = fmaf(WA, d.x0, fmaf(WB, d.x1, WA * d.x2));
    hx[1]  = fmaf(WA, d.x1, fmaf(WB, d.x2, WA * d.x3));
    hy[0]  = fmaf(WA, d.y0, fmaf(WB, d.y1, WA * d.y2));
    hy[1]  = fmaf(WA, d.y1, fmaf(WB, d.y2, WA * d.y3));
    hxx[0] = fmaf(WA, q0,   fmaf(WB, q1,   WA * q2));
    hxx[1] = fmaf(WA, q1,   fmaf(WB, q2,   WA * q3));
    hyy[0] = fmaf(WA, r0,   fmaf(WB, r1,   WA * r2));
    hyy[1] = fmaf(WA, r1,   fmaf(WB, r2,   WA * r3));
}

__device__ __forceinline__ float colW(int c) {
    if (c > 507) return 0.0f;
    if (c == 5 || c == 506) return WAB;
    if (c == 507) return WA;
    return 1.0f;
}

__global__ void __launch_bounds__(128, 7)
loss_kernel(const float* __restrict__ X, const float* __restrict__ Y,
            float* __restrict__ out) {
    const int lane = threadIdx.x & 31;
    const int wid  = threadIdx.x >> 5;
    const int unit = blockIdx.x * 4 + wid;   // 4096 warp units
    const int b = unit >> 6;                 // image
    const int s = (unit >> 3) & 7;           // col stripe (64 output cols)
    const int t = unit & 7;                  // row strip (64 output rows)

    const int r0   = 5 + 64 * t;
    const int rend = min(r0 + 64, 507);      // outputs rows r0..rend-1
    const int j0   = 5 + 64 * s + 2 * lane;  // first of 2 output cols
    const int ib   = min(j0 - 1, 508);       // aligned float2 bases (even)
    const int hb   = min(j0 + 1, 510);

    const bool t0 = (t == 0), t7 = (t == 7);
    const bool s0warp = (s == 0);
    const int  own_end = t7 ? 0x7FFFFFFF : r0 + 62;  // xy row ownership

    const float* xp = X + ((size_t)b << 18) + (size_t)(r0 - 1) * 512;
    const float* yp = Y + ((size_t)b << 18) + (size_t)(r0 - 1) * 512;

    const float mk0  = (j0     <= 506) ? 1.0f : 0.0f;
    const float mk1  = (j0 + 1 <= 506) ? 1.0f : 0.0f;
    const float mk20 = 2.0f * mk0, mk21 = 2.0f * mk1;
    const float w1 = colW(j0), w2 = colW(j0 + 1);
    const float w0 = (s == 0 && lane == 0) ? WA : 0.0f;  // input col 4

    float hx[2], hy[2], hxx[2], hyy[2];
    float Vpx[2], Vpy[2], Vpxx[2], Vpyy[2];
    float Vqx[2], Vqy[2], Vqxx[2], Vqyy[2];
    float accP = 0.0f, accC = 0.0f;

    // ---- prime: input row r0-1 seeds Vq; xy contribution (rw: row 4 -> WA)
    RowD cur = ldrow(xp, yp, ib, hb);
    {
        htap(cur, hx, hy, hxx, hyy);
#pragma unroll
        for (int k = 0; k < 2; k++) {
            Vqx[k] = WA * hx[k];  Vqy[k]  = WA * hy[k];
            Vqxx[k] = WA * hxx[k]; Vqyy[k] = WA * hyy[k];
        }
        float rxy = fmaf(w2, cur.x2 * cur.y2, w1 * (cur.x1 * cur.y1));
        if (s0warp) rxy = fmaf(w0, cur.x0 * cur.y0, rxy);
        float rw = t0 ? WA : 1.0f;
        accC = fmaf(-2.0f * rw, rxy, accC);
    }
    xp += 512; yp += 512;
    // ---- prime: input row r0 -> Vp for output r0; xy (row 5 -> WA+WB)
    cur = ldrow(xp, yp, ib, hb);
    {
        htap(cur, hx, hy, hxx, hyy);
#pragma unroll
        for (int k = 0; k < 2; k++) {
            Vpx[k]  = fmaf(WB, hx[k],  Vqx[k]);   Vqx[k]  = WA * hx[k];
            Vpy[k]  = fmaf(WB, hy[k],  Vqy[k]);   Vqy[k]  = WA * hy[k];
            Vpxx[k] = fmaf(WB, hxx[k], Vqxx[k]);  Vqxx[k] = WA * hxx[k];
            Vpyy[k] = fmaf(WB, hyy[k], Vqyy[k]);  Vqyy[k] = WA * hyy[k];
        }
        float rxy = fmaf(w2, cur.x2 * cur.y2, w1 * (cur.x1 * cur.y1));
        if (s0warp) rxy = fmaf(w0, cur.x0 * cur.y0, rxy);
        float rw = t0 ? WAB : 1.0f;
        accC = fmaf(-2.0f * rw, rxy, accC);
    }
    xp += 512; yp += 512;
    cur = ldrow(xp, yp, ib, hb);   // row r0+1

#pragma unroll 2
    for (int i = r0 + 1; i <= rend; ++i) {
        xp += 512; yp += 512;
        RowD nxt = ldrow(xp, yp, ib, hb);   // row i+1; over-read <=508, in-bounds

        htap(cur, hx, hy, hxx, hyy);
        float rxy = fmaf(w2, cur.x2 * cur.y2, w1 * (cur.x1 * cur.y1));
        if (s0warp) rxy = fmaf(w0, cur.x0 * cur.y0, rxy);
        float rw = (i <= own_end) ? 1.0f : 0.0f;
        if (t7 && i >= 506) rw = (i == 506) ? WAB : WA;

        // finish output row i-1 (all imm-form FFMA) + epilogue terms
#pragma unroll
        for (int k = 0; k < 2; ++k) {
            float vx  = fmaf(WA, hx[k],  Vpx[k]);
            float vy  = fmaf(WA, hy[k],  Vpy[k]);
            float vxx = fmaf(WA, hxx[k], Vpxx[k]);
            float vyy = fmaf(WA, hyy[k], Vpyy[k]);
            float sxx = fmaf(-vx, vx, vxx);
            float syy = fmaf(-vy, vy, vyy);
            accP = fmaf(k ? mk1  : mk0,  sxx * syy, accP);
            accC = fmaf(k ? mk21 : mk20, vx * vy,   accC);
            Vpx[k]  = fmaf(WB, hx[k],  Vqx[k]);   Vqx[k]  = WA * hx[k];
            Vpy[k]  = fmaf(WB, hy[k],  Vqy[k]);   Vqy[k]  = WA * hy[k];
            Vpxx[k] = fmaf(WB, hxx[k], Vqxx[k]);  Vqxx[k] = WA * hxx[k];
            Vpyy[k] = fmaf(WB, hyy[k], Vqyy[k]);  Vqyy[k] = WA * hyy[k];
        }
        accC = fmaf(-2.0f * rw, rxy, accC);
        cur = nxt;
    }

    // warp -> block -> grid reduction (last block finalizes)
    float acs = accP + accC;
#pragma unroll
    for (int o = 16; o > 0; o >>= 1) acs += __shfl_xor_sync(FULLMASK, acs, o);

    __shared__ float sp[4];
    __shared__ bool is_last;
    __shared__ double sh[128];
    if (lane == 0) sp[wid] = acs;
    __syncthreads();
    if (threadIdx.x == 0) {
        g_part[blockIdx.x] = (sp[0] + sp[1]) + (sp[2] + sp[3]);
        __threadfence();
        unsigned r = atomicAdd(&g_cnt, 1u);
        is_last = (r == gridDim.x - 1);
    }
    __syncthreads();
    if (is_last) {
        __threadfence();
        double ds = 0.0;
#pragma unroll
        for (int i = threadIdx.x; i < 1024; i += 128) ds += (double)g_part[i];
        sh[threadIdx.x] = ds;
        __syncthreads();
        for (int o = 64; o > 0; o >>= 1) {
            if (threadIdx.x < o) sh[threadIdx.x] += sh[threadIdx.x + o];
            __syncthreads();
        }
        if (threadIdx.x == 0) {
            out[0] = (float)(sh[0] * (1.0 / 252004.0));
            g_cnt = 0;   // reset for next graph replay (deterministic)
        }
    }
}

extern "C" void kernel_launch(void* const* d_in, const int* in_sizes, int n_in,
                              void* d_out, int out_size) {
    const float* X = (const float*)d_in[0];
    const float* Y = (const float*)d_in[1];
    float* out = (float*)d_out;

    // 4096 warps = 64 images x 8 col-stripes(64) x 8 row-strips(64); 4 warps/block
    loss_kernel<<<1024, 128>>>(X, Y, out);
}